// round 4
// baseline (speedup 1.0000x reference)
#include <cuda_runtime.h>
#include <math.h>
#include <stdint.h>

// ---------------- problem constants ----------------
#define HH      14
#define LL      196            // H*W
#define EMBED   768
#define DIMM    3072           // 4*EMBED
#define DINN    6144           // 2*DIM
#define DTRr    192
#define DSTt    16
#define DCONV   4
#define BATCH   2
#define MROWS   392            // BATCH*LL
#define XPROJ_N 224            // DTR + 2*DST

// ---------------- scratch (device globals; no allocations) ----------------
__device__ float g_col[MROWS * EMBED];
__device__ float g_xe [MROWS * EMBED];
__device__ float g_xm [MROWS * DIMM];
__device__ float g_xln[MROWS * DIMM];
__device__ float g_xr [MROWS * 2 * DINN];
__device__ float g_xs [MROWS * DINN];
__device__ float g_dbl[MROWS * XPROJ_N];
__device__ float g_dt [MROWS * DINN];
__device__ float g_y  [MROWS * DINN];
__device__ float g_xp [MROWS * EMBED];
__device__ int   g_sp[LL];
__device__ int   g_ra[LL];
__device__ int   g_bd[LL];

// ---------------- helpers ----------------
__device__ __forceinline__ float sigmoidf_(float v) { return 1.0f / (1.0f + expf(-v)); }
__device__ __forceinline__ float softplusf_(float v) {
    return v > 0.0f ? v + log1pf(expf(-v)) : log1pf(expf(v));
}

// ---------------- index tables (replicates numpy double-precision exactly) ----------------
__global__ void compute_indices_kernel() {
    __shared__ double sdd[LL];
    __shared__ double saa[LL];
    __shared__ int    cand[202];
    __shared__ unsigned char seen[LL];
    const int tid = threadIdx.x;
    const double TWO_PI = 2.0 * 3.14159265358979323846;

    // spiral candidates (202 of them), in parallel
    if (tid < 202) {
        int r = 0, rem = tid;
        for (;;) {
            int c = (2 * r > 8) ? 2 * r : 8;
            if (rem < c) break;
            rem -= c; r++;
        }
        int nang = (2 * r > 8) ? 2 * r : 8;
        double step = TWO_PI / (double)nang;
        double ang = (double)rem * step;
        double hh = 7.0 + (double)r * cos(ang);
        double ww = 7.0 + (double)r * sin(ang);
        int h = (int)hh;   // trunc toward zero == python int()
        int w = (int)ww;
        cand[tid] = (h >= 0 && h < HH && w >= 0 && w < HH) ? (h * HH + w) : -1;
    }
    if (tid < LL) {
        seen[tid] = 0;
        int h = tid / HH, w = tid % HH;
        double dy = (double)(h - 7), dx = (double)(w - 7);
        sdd[tid] = sqrt(dy * dy + dx * dx);
        saa[tid] = atan2(dy, dx);
    }
    __syncthreads();

    if (tid == 0) {
        // spiral: dedup in order, then remaining ascending
        int cnt = 0;
        for (int i = 0; i < 202; i++) {
            int c = cand[i];
            if (c >= 0 && !seen[c]) { seen[c] = 1; g_sp[cnt++] = c; }
        }
        for (int i = 0; i < LL; i++)
            if (!seen[i]) g_sp[cnt++] = i;
        // boundary
        int bc = 0;
        for (int i = 0; i < LL; i++) {
            int h = i / HH, w = i % HH;
            if (h == 0 || h == HH - 1 || w == 0 || w == HH - 1) g_bd[bc++] = i;
        }
        for (int i = 0; i < LL; i++) {
            int h = i / HH, w = i % HH;
            if (!(h == 0 || h == HH - 1 || w == 0 || w == HH - 1)) g_bd[bc++] = i;
        }
    }
    // radial: parallel rank sort by (-d, a), stable
    if (tid < LL) {
        double di = sdd[tid], ai = saa[tid];
        int rank = 0;
        for (int j = 0; j < LL; j++) {
            double dj = sdd[j], aj = saa[j];
            bool before = (dj > di) ||
                          (dj == di && (aj < ai || (aj == ai && j < tid)));
            rank += before ? 1 : 0;
        }
        g_ra[rank] = tid;
    }
}

// ---------------- im2col for patch embedding ----------------
__global__ void im2col_kernel(const float* __restrict__ x) {
    int idx = blockIdx.x * blockDim.x + threadIdx.x;
    if (idx >= MROWS * EMBED) return;
    int m = idx / EMBED;       // b*196 + l
    int k = idx % EMBED;       // c*256 + i*16 + j
    int b = m / LL, l = m % LL;
    int ph = l / HH, pw = l % HH;
    int c = k / 256, rem = k % 256;
    int i = rem / 16, j = rem % 16;
    g_col[idx] = x[(((size_t)(b * 3 + c) * 224) + (ph * 16 + i)) * 224 + (pw * 16 + j)];
}

// ---------------- generic tiled SGEMM: C[M,N] = A[M,K] * B[N,K]^T ----------------
// act: 0=none, 1=softplus. beta: 0=store, 1=accumulate.
#define BMt 64
#define BNt 64
#define BKt 16
__global__ __launch_bounds__(256)
void sgemm_nt(const float* __restrict__ A, int lda,
              const float* __restrict__ B,
              float* __restrict__ C,
              int M, int N, int K,
              const float* __restrict__ bias,
              int act, int beta)
{
    __shared__ float As[BKt][BMt + 4];
    __shared__ float Bs[BKt][BNt + 4];
    const int tid = threadIdx.x;
    const int bm0 = blockIdx.y * BMt;
    const int bn0 = blockIdx.x * BNt;
    const int lr = tid >> 2;          // 0..63 row-in-tile for loading
    const int lc = (tid & 3) << 2;    // 0,4,8,12 k-offset
    const int tn = (tid & 15) << 2;   // compute col base
    const int tm = (tid >> 4) << 2;   // compute row base

    float acc[4][4];
#pragma unroll
    for (int i = 0; i < 4; i++)
#pragma unroll
        for (int j = 0; j < 4; j++) acc[i][j] = 0.0f;

    for (int k0 = 0; k0 < K; k0 += BKt) {
        float4 av = make_float4(0.f, 0.f, 0.f, 0.f);
        int ar = bm0 + lr;
        if (ar < M)
            av = *reinterpret_cast<const float4*>(A + (size_t)ar * lda + k0 + lc);
        As[lc + 0][lr] = av.x; As[lc + 1][lr] = av.y;
        As[lc + 2][lr] = av.z; As[lc + 3][lr] = av.w;

        float4 bv = make_float4(0.f, 0.f, 0.f, 0.f);
        int br = bn0 + lr;
        if (br < N)
            bv = *reinterpret_cast<const float4*>(B + (size_t)br * K + k0 + lc);
        Bs[lc + 0][lr] = bv.x; Bs[lc + 1][lr] = bv.y;
        Bs[lc + 2][lr] = bv.z; Bs[lc + 3][lr] = bv.w;
        __syncthreads();

#pragma unroll
        for (int k = 0; k < BKt; k++) {
            float4 a = *reinterpret_cast<const float4*>(&As[k][tm]);
            float4 b = *reinterpret_cast<const float4*>(&Bs[k][tn]);
            acc[0][0] += a.x * b.x; acc[0][1] += a.x * b.y; acc[0][2] += a.x * b.z; acc[0][3] += a.x * b.w;
            acc[1][0] += a.y * b.x; acc[1][1] += a.y * b.y; acc[1][2] += a.y * b.z; acc[1][3] += a.y * b.w;
            acc[2][0] += a.z * b.x; acc[2][1] += a.z * b.y; acc[2][2] += a.z * b.z; acc[2][3] += a.z * b.w;
            acc[3][0] += a.w * b.x; acc[3][1] += a.w * b.y; acc[3][2] += a.w * b.z; acc[3][3] += a.w * b.w;
        }
        __syncthreads();
    }

#pragma unroll
    for (int i = 0; i < 4; i++) {
        int m = bm0 + tm + i;
        if (m >= M) continue;
#pragma unroll
        for (int j = 0; j < 4; j++) {
            int n = bn0 + tn + j;
            if (n >= N) continue;
            float v = acc[i][j];
            if (bias) v += bias[n];
            if (act == 1) v = softplusf_(v);
            float* p = C + (size_t)m * N + n;
            if (beta) *p += v; else *p = v;
        }
    }
}

// ---------------- add pos_embed + abcde projection into xe ----------------
__global__ void add_pos_ab_kernel(const float* __restrict__ pos_embed,
                                  const float* __restrict__ abcde_features,
                                  const float* __restrict__ abcde_w,
                                  const float* __restrict__ abcde_b)
{
    int idx = blockIdx.x * blockDim.x + threadIdx.x;
    if (idx >= MROWS * EMBED) return;
    int m = idx / EMBED;
    int e = idx % EMBED;
    int b = m / LL, l = m % LL;
    float ab = abcde_b[e];
#pragma unroll
    for (int k = 0; k < 5; k++)
        ab += abcde_features[b * 5 + k] * abcde_w[e * 5 + k];
    g_xe[idx] += pos_embed[l * EMBED + e] + ab;
}

// ---------------- gather 4 orderings into xm ----------------
__global__ void gather_kernel() {
    int idx = blockIdx.x * blockDim.x + threadIdx.x;
    if (idx >= MROWS * DIMM) return;
    int m = idx / DIMM;
    int c = idx % DIMM;
    int b = m / LL, l = m % LL;
    int s = c / EMBED, e = c % EMBED;
    int src_l = (s == 0) ? g_sp[l] : (s == 1) ? g_ra[l] : (s == 2) ? g_bd[l] : l;
    g_xm[idx] = g_xe[((size_t)(b * LL + src_l)) * EMBED + e];
}

// ---------------- layernorm (generic width) ----------------
__global__ void ln_kernel(const float* __restrict__ in, float* __restrict__ out,
                          const float* __restrict__ w, const float* __restrict__ b,
                          int width)
{
    __shared__ float red[256];
    __shared__ float s_mean, s_rstd;
    const int row = blockIdx.x;
    const float* x = in + (size_t)row * width;
    float s = 0.0f;
    for (int j = threadIdx.x; j < width; j += 256) s += x[j];
    red[threadIdx.x] = s; __syncthreads();
    for (int off = 128; off > 0; off >>= 1) {
        if (threadIdx.x < off) red[threadIdx.x] += red[threadIdx.x + off];
        __syncthreads();
    }
    if (threadIdx.x == 0) s_mean = red[0] / (float)width;
    __syncthreads();
    float m = s_mean;
    float vs = 0.0f;
    for (int j = threadIdx.x; j < width; j += 256) {
        float d = x[j] - m; vs += d * d;
    }
    red[threadIdx.x] = vs; __syncthreads();
    for (int off = 128; off > 0; off >>= 1) {
        if (threadIdx.x < off) red[threadIdx.x] += red[threadIdx.x + off];
        __syncthreads();
    }
    if (threadIdx.x == 0) s_rstd = rsqrtf(red[0] / (float)width + 1e-5f);
    __syncthreads();
    float r = s_rstd;
    float* o = out + (size_t)row * width;
    for (int j = threadIdx.x; j < width; j += 256)
        o[j] = (x[j] - m) * r * w[j] + b[j];
}

// ---------------- causal depthwise conv (4 taps) + bias + silu ----------------
__global__ void conv_silu_kernel(const float* __restrict__ conv_w,
                                 const float* __restrict__ conv_b)
{
    int idx = blockIdx.x * blockDim.x + threadIdx.x;
    if (idx >= MROWS * DINN) return;
    int row = idx / DINN;      // b*196 + t
    int d   = idx % DINN;
    int b = row / LL, t = row % LL;
    float acc = conv_b[d];
#pragma unroll
    for (int j = 0; j < DCONV; j++) {
        int tt = t - (DCONV - 1) + j;
        if (tt >= 0)
            acc += conv_w[d * DCONV + j] * g_xr[((size_t)(b * LL + tt)) * (2 * DINN) + d];
    }
    g_xs[idx] = acc * sigmoidf_(acc);
}

// ---------------- selective scan: one thread per (b, d, n) ----------------
__global__ void scan_kernel(const float* __restrict__ A_log,
                            const float* __restrict__ D_param)
{
    const int g = blockIdx.x * blockDim.x + threadIdx.x;  // 2*6144*16 threads
    const int n  = g & 15;
    const int dg = g >> 4;            // 0..12287
    const int d  = dg % DINN;
    const int b  = dg / DINN;

    const float Alog2 = -expf(A_log[d * DSTt + n]) * 1.4426950408889634f; // A*log2(e)
    const float Dd = D_param[d];

    float st = 0.0f;
#pragma unroll 1
    for (int t = 0; t < LL; t++) {
        const size_t row = (size_t)(b * LL + t);
        const float dtv = g_dt[row * DINN + d];
        const float xv  = g_xs[row * DINN + d];
        const float Bv  = g_dbl[row * XPROJ_N + DTRr + n];
        const float Cv  = g_dbl[row * XPROJ_N + DTRr + DSTt + n];
        st = st * exp2f(dtv * Alog2) + dtv * Bv * xv;
        float p = st * Cv;
        p += __shfl_xor_sync(0xffffffffu, p, 1, 16);
        p += __shfl_xor_sync(0xffffffffu, p, 2, 16);
        p += __shfl_xor_sync(0xffffffffu, p, 4, 16);
        p += __shfl_xor_sync(0xffffffffu, p, 8, 16);
        if (n == 0) {
            float res = g_xr[row * (2 * DINN) + DINN + d];
            float y = (p + xv * Dd) * (res * sigmoidf_(res));
            g_y[row * DINN + d] = y;
        }
    }
}

// ---------------- final mean over L ----------------
__global__ void mean_kernel(float* __restrict__ out) {
    int idx = blockIdx.x * blockDim.x + threadIdx.x;
    if (idx >= BATCH * EMBED) return;
    int b = idx / EMBED, e = idx % EMBED;
    float s = 0.0f;
    for (int l = 0; l < LL; l++)
        s += g_xp[((size_t)(b * LL + l)) * EMBED + e];
    out[idx] = s / (float)LL;
}

// ---------------- launch ----------------
extern "C" void kernel_launch(void* const* d_in, const int* in_sizes, int n_in,
                              void* d_out, int out_size)
{
    // order disambiguation: index 14 is A_log (2*6144*16=196608) in dict order,
    // dt_proj_b (12288) in reference-signature order.
    const bool dictOrder = (in_sizes[14] == 2 * DINN * DSTt);

    const float* x          = (const float*)d_in[0];
    const float* abcde_feat = (const float*)d_in[1];
    const float* patch_w    = (const float*)d_in[2];
    const float* patch_b    = (const float*)d_in[3];
    const float* pos_embed  = (const float*)d_in[4];
    const float* abcde_w    = (const float*)d_in[5];
    const float* abcde_b    = (const float*)d_in[6];
    const float* ln_w       = (const float*)d_in[7];
    const float* ln_b       = (const float*)d_in[8];
    const float* in_proj_w  = (const float*)d_in[9];
    const float* conv_w     = (const float*)d_in[10];
    const float* conv_b     = (const float*)d_in[11];
    const float* x_proj_w   = (const float*)d_in[12];
    const float* dt_proj_w  = (const float*)d_in[13];
    const float* dt_proj_b  = dictOrder ? (const float*)d_in[21] : (const float*)d_in[14];
    const float* A_log      = dictOrder ? (const float*)d_in[14] : (const float*)d_in[15];
    const float* D_param    = dictOrder ? (const float*)d_in[15] : (const float*)d_in[16];
    const float* out_proj_w = dictOrder ? (const float*)d_in[16] : (const float*)d_in[17];
    const float* proj_w     = dictOrder ? (const float*)d_in[17] : (const float*)d_in[18];
    const float* proj_b     = dictOrder ? (const float*)d_in[18] : (const float*)d_in[19];
    const float* norm_w     = dictOrder ? (const float*)d_in[19] : (const float*)d_in[20];
    const float* norm_b     = dictOrder ? (const float*)d_in[20] : (const float*)d_in[21];

    float* out = (float*)d_out;

    float* p_col; cudaGetSymbolAddress((void**)&p_col, g_col);
    float* p_xe;  cudaGetSymbolAddress((void**)&p_xe,  g_xe);
    float* p_xm;  cudaGetSymbolAddress((void**)&p_xm,  g_xm);
    float* p_xln; cudaGetSymbolAddress((void**)&p_xln, g_xln);
    float* p_xr;  cudaGetSymbolAddress((void**)&p_xr,  g_xr);
    float* p_xs;  cudaGetSymbolAddress((void**)&p_xs,  g_xs);
    float* p_dbl; cudaGetSymbolAddress((void**)&p_dbl, g_dbl);
    float* p_dt;  cudaGetSymbolAddress((void**)&p_dt,  g_dt);
    float* p_y;   cudaGetSymbolAddress((void**)&p_y,   g_y);
    float* p_xp;  cudaGetSymbolAddress((void**)&p_xp,  g_xp);

    // 1. index tables
    compute_indices_kernel<<<1, 256>>>();

    // 2. patch embedding: im2col + GEMM(+bias)
    im2col_kernel<<<(MROWS * EMBED + 255) / 256, 256>>>(x);
    {
        dim3 grid((EMBED + BNt - 1) / BNt, (MROWS + BMt - 1) / BMt);
        sgemm_nt<<<grid, 256>>>(p_col, EMBED, patch_w, p_xe,
                                MROWS, EMBED, EMBED, patch_b, 0, 0);
    }
    add_pos_ab_kernel<<<(MROWS * EMBED + 255) / 256, 256>>>(pos_embed, abcde_feat, abcde_w, abcde_b);
    gather_kernel<<<(MROWS * DIMM + 255) / 256, 256>>>();

    // 3. mamba layers
    for (int l = 0; l < 2; l++) {
        const float* w_in  = in_proj_w  + (size_t)l * 2 * DINN * DIMM;
        const float* w_cv  = conv_w     + (size_t)l * DINN * DCONV;
        const float* b_cv  = conv_b     + (size_t)l * DINN;
        const float* w_xp  = x_proj_w   + (size_t)l * XPROJ_N * DINN;
        const float* w_dt  = dt_proj_w  + (size_t)l * DINN * DTRr;
        const float* b_dt  = dt_proj_b  + (size_t)l * DINN;
        const float* w_out = out_proj_w + (size_t)l * DIMM * DINN;
        const float* Al    = A_log      + (size_t)l * DINN * DSTt;
        const float* Dl    = D_param    + (size_t)l * DINN;

        ln_kernel<<<MROWS, 256>>>(p_xm, p_xln, ln_w + l * DIMM, ln_b + l * DIMM, DIMM);

        {   // in_proj: [392,3072] x [12288,3072]^T -> [392,12288]
            dim3 grid((2 * DINN + BNt - 1) / BNt, (MROWS + BMt - 1) / BMt);
            sgemm_nt<<<grid, 256>>>(p_xln, DIMM, w_in, p_xr,
                                    MROWS, 2 * DINN, DIMM, nullptr, 0, 0);
        }

        conv_silu_kernel<<<(MROWS * DINN + 255) / 256, 256>>>(w_cv, b_cv);

        {   // x_proj: [392,6144] x [224,6144]^T -> [392,224]
            dim3 grid((XPROJ_N + BNt - 1) / BNt, (MROWS + BMt - 1) / BMt);
            sgemm_nt<<<grid, 256>>>(p_xs, DINN, w_xp, p_dbl,
                                    MROWS, XPROJ_N, DINN, nullptr, 0, 0);
        }

        {   // dt_proj + bias + softplus: [392,192] x [6144,192]^T -> [392,6144]
            dim3 grid((DINN + BNt - 1) / BNt, (MROWS + BMt - 1) / BMt);
            sgemm_nt<<<grid, 256>>>(p_dbl, XPROJ_N, w_dt, p_dt,
                                    MROWS, DINN, DTRr, b_dt, 1, 0);
        }

        scan_kernel<<<(BATCH * DINN * DSTt) / 256, 256>>>(Al, Dl);

        {   // out_proj with residual accumulate into xm
            dim3 grid((DIMM + BNt - 1) / BNt, (MROWS + BMt - 1) / BMt);
            sgemm_nt<<<grid, 256>>>(p_y, DINN, w_out, p_xm,
                                    MROWS, DIMM, DINN, nullptr, 0, 1);
        }
    }

    // 4. final projection + LN + mean
    {
        dim3 grid((EMBED + BNt - 1) / BNt, (MROWS + BMt - 1) / BMt);
        sgemm_nt<<<grid, 256>>>(p_xm, DIMM, proj_w, p_xp,
                                MROWS, EMBED, DIMM, proj_b, 0, 0);
    }
    ln_kernel<<<MROWS, 256>>>(p_xp, p_xp, norm_w, norm_b, EMBED);
    mean_kernel<<<(BATCH * EMBED + 255) / 256, 256>>>(out);

    (void)n_in; (void)out_size;
}

// round 7
// speedup vs baseline: 1.9283x; 1.9283x over previous
#include <cuda_runtime.h>
#include <math.h>
#include <stdint.h>

// ---------------- problem constants ----------------
#define HH      14
#define LL      196            // H*W
#define EMBED   768
#define DIMM    3072           // 4*EMBED
#define DINN    6144           // 2*DIM
#define DTRr    192
#define DSTt    16
#define DCONV   4
#define BATCH   2
#define MROWS   392            // BATCH*LL
#define XPROJ_N 224            // DTR + 2*DST

// ---------------- scratch (device globals; no allocations) ----------------
__device__ float g_col[MROWS * EMBED];
__device__ float g_xe [MROWS * EMBED];
__device__ float g_xm [MROWS * DIMM];
__device__ float g_xln[MROWS * DIMM];
__device__ float g_xr [MROWS * 2 * DINN];
__device__ float g_xs [MROWS * DINN];
__device__ float g_dbl[MROWS * XPROJ_N];
__device__ float g_dt [MROWS * DINN];
__device__ float g_y  [MROWS * DINN];
__device__ float g_xp [MROWS * EMBED];
__device__ int   g_sp[LL];
__device__ int   g_ra[LL];
__device__ int   g_bd[LL];

// ---------------- helpers ----------------
__device__ __forceinline__ float sigmoidf_(float v) { return 1.0f / (1.0f + expf(-v)); }
__device__ __forceinline__ float softplusf_(float v) {
    return v > 0.0f ? v + log1pf(expf(-v)) : log1pf(expf(v));
}
__device__ __forceinline__ uint32_t f2tf32(float f) {
    uint32_t r;
    asm("cvt.rna.tf32.f32 %0, %1;" : "=r"(r) : "f"(f));
    return r;
}
__device__ __forceinline__ void mma_tf32(float* c, const uint32_t* a, const uint32_t* b) {
    asm volatile(
        "mma.sync.aligned.m16n8k8.row.col.f32.tf32.tf32.f32 "
        "{%0,%1,%2,%3}, {%4,%5,%6,%7}, {%8,%9}, {%0,%1,%2,%3};"
        : "+f"(c[0]), "+f"(c[1]), "+f"(c[2]), "+f"(c[3])
        : "r"(a[0]), "r"(a[1]), "r"(a[2]), "r"(a[3]), "r"(b[0]), "r"(b[1]));
}
__device__ __forceinline__ void cp_async16(uint32_t dst_smem, const float* src) {
    asm volatile("cp.async.ca.shared.global [%0], [%1], 16;"
                 :: "r"(dst_smem), "l"(__cvta_generic_to_global(src)) : "memory");
}
__device__ __forceinline__ void cp_commit() {
    asm volatile("cp.async.commit_group;" ::: "memory");
}
__device__ __forceinline__ void cp_wait1() {
    asm volatile("cp.async.wait_group 1;" ::: "memory");
}
__device__ __forceinline__ void cp_wait0() {
    asm volatile("cp.async.wait_group 0;" ::: "memory");
}

// ================= tensor-core GEMM (mma.sync tf32): C[M,N] = A[M,K]*B[N,K]^T =================
// tile 128x128, K-stage 32. 256 threads = 8 warps in 2(M)x4(N); warp tile 64x32.
// act: 0=none, 1=softplus. beta: 0=store, 1=accumulate.
#define TMt 128
#define TNt 128
#define TKt 32
#define APITCH 36                    // floats; bank = (4*row + k) % 32 -> conflict-free frags
#define ABUF   (TMt * APITCH)        // floats per A (or B) buffer
#define SMEMSZ (4 * ABUF * 4)        // bytes: 2 stages x (A+B)

__global__ __launch_bounds__(256, 2)
void tc_gemm_nt(const float* __restrict__ A, int lda,
                const float* __restrict__ B,
                float* __restrict__ C,
                int M, int N, int K,
                const float* __restrict__ bias,
                int act, int beta)
{
    extern __shared__ float smem[];
    const int tid  = threadIdx.x;
    const int wid  = tid >> 5;
    const int lane = tid & 31;
    const int g = lane >> 2;         // group id 0..7
    const int t = lane & 3;          // thread-in-group
    const int bm0 = blockIdx.y * TMt;
    const int bn0 = blockIdx.x * TNt;
    const int wm0 = (wid >> 2) * 64; // warp M offset in tile
    const int wn0 = (wid & 3) * 32;  // warp N offset in tile

    float* bufs[4] = { smem, smem + ABUF, smem + 2 * ABUF, smem + 3 * ABUF };
    const uint32_t sbase = (uint32_t)__cvta_generic_to_shared(smem);

    // loader: 4 float4 per thread per operand per stage
    int lm[4], lk[4];
#pragma unroll
    for (int i = 0; i < 4; i++) {
        int idx = tid + i * 256;
        lm[i] = idx >> 3;            // 0..127 row in tile
        lk[i] = (idx & 7) << 2;      // k offset 0,4,...,28
    }

    auto load_stage = [&](int k0, int stage) {
        const uint32_t adst0 = sbase + (uint32_t)(2 * stage) * (ABUF * 4);
        const uint32_t bdst0 = adst0 + ABUF * 4;
#pragma unroll
        for (int i = 0; i < 4; i++) {
            int ar = bm0 + lm[i]; if (ar > M - 1) ar = M - 1;
            cp_async16(adst0 + (uint32_t)(lm[i] * APITCH + lk[i]) * 4,
                       A + (size_t)ar * lda + k0 + lk[i]);
            int br = bn0 + lm[i]; if (br > N - 1) br = N - 1;
            cp_async16(bdst0 + (uint32_t)(lm[i] * APITCH + lk[i]) * 4,
                       B + (size_t)br * K + k0 + lk[i]);
        }
        cp_commit();
    };

    float c[4][4][4];
#pragma unroll
    for (int mi = 0; mi < 4; mi++)
#pragma unroll
        for (int ni = 0; ni < 4; ni++)
#pragma unroll
            for (int r = 0; r < 4; r++) c[mi][ni][r] = 0.0f;

    const int ns = K / TKt;
    load_stage(0, 0);

    for (int s = 0; s < ns; s++) {
        const int buf = s & 1;
        if (s + 1 < ns) load_stage((s + 1) * TKt, buf ^ 1);
        if (s + 1 < ns) cp_wait1(); else cp_wait0();
        __syncthreads();

        const float* As = bufs[2 * buf];
        const float* Bs = bufs[2 * buf + 1];
#pragma unroll
        for (int ka = 0; ka < 4; ka++) {
            const int kb = ka * 8;
            uint32_t af[4][4], bf[4][2];
#pragma unroll
            for (int mi = 0; mi < 4; mi++) {
                const int r = wm0 + mi * 16 + g;
                af[mi][0] = f2tf32(As[r * APITCH + kb + t]);
                af[mi][1] = f2tf32(As[(r + 8) * APITCH + kb + t]);
                af[mi][2] = f2tf32(As[r * APITCH + kb + t + 4]);
                af[mi][3] = f2tf32(As[(r + 8) * APITCH + kb + t + 4]);
            }
#pragma unroll
            for (int ni = 0; ni < 4; ni++) {
                const int n = wn0 + ni * 8 + g;
                bf[ni][0] = f2tf32(Bs[n * APITCH + kb + t]);
                bf[ni][1] = f2tf32(Bs[n * APITCH + kb + t + 4]);
            }
#pragma unroll
            for (int mi = 0; mi < 4; mi++)
#pragma unroll
                for (int ni = 0; ni < 4; ni++)
                    mma_tf32(c[mi][ni], af[mi], bf[ni]);
        }
        __syncthreads();
    }

    // epilogue
#pragma unroll
    for (int mi = 0; mi < 4; mi++) {
        const int row0 = bm0 + wm0 + mi * 16 + g;
#pragma unroll
        for (int ni = 0; ni < 4; ni++) {
            const int col0 = bn0 + wn0 + ni * 8 + 2 * t;
#pragma unroll
            for (int r = 0; r < 4; r++) {
                const int row = row0 + ((r >> 1) << 3);   // +8 for r=2,3
                const int col = col0 + (r & 1);
                if (row < M && col < N) {
                    float v = c[mi][ni][r];
                    if (bias) v += bias[col];
                    if (act == 1) v = softplusf_(v);
                    float* p = C + (size_t)row * N + col;
                    if (beta) *p += v; else *p = v;
                }
            }
        }
    }
}

// ---------------- index tables (replicates numpy double-precision exactly) ----------------
__global__ void compute_indices_kernel() {
    __shared__ double sdd[LL];
    __shared__ double saa[LL];
    __shared__ int    cand[202];
    __shared__ unsigned char seen[LL];
    const int tid = threadIdx.x;
    const double TWO_PI = 2.0 * 3.14159265358979323846;

    if (tid < 202) {
        int r = 0, rem = tid;
        for (;;) {
            int c = (2 * r > 8) ? 2 * r : 8;
            if (rem < c) break;
            rem -= c; r++;
        }
        int nang = (2 * r > 8) ? 2 * r : 8;
        double step = TWO_PI / (double)nang;
        double ang = (double)rem * step;
        double hh = 7.0 + (double)r * cos(ang);
        double ww = 7.0 + (double)r * sin(ang);
        int h = (int)hh;
        int w = (int)ww;
        cand[tid] = (h >= 0 && h < HH && w >= 0 && w < HH) ? (h * HH + w) : -1;
    }
    if (tid < LL) {
        seen[tid] = 0;
        int h = tid / HH, w = tid % HH;
        double dy = (double)(h - 7), dx = (double)(w - 7);
        sdd[tid] = sqrt(dy * dy + dx * dx);
        saa[tid] = atan2(dy, dx);
    }
    __syncthreads();

    if (tid == 0) {
        int cnt = 0;
        for (int i = 0; i < 202; i++) {
            int c = cand[i];
            if (c >= 0 && !seen[c]) { seen[c] = 1; g_sp[cnt++] = c; }
        }
        for (int i = 0; i < LL; i++)
            if (!seen[i]) g_sp[cnt++] = i;
        int bc = 0;
        for (int i = 0; i < LL; i++) {
            int h = i / HH, w = i % HH;
            if (h == 0 || h == HH - 1 || w == 0 || w == HH - 1) g_bd[bc++] = i;
        }
        for (int i = 0; i < LL; i++) {
            int h = i / HH, w = i % HH;
            if (!(h == 0 || h == HH - 1 || w == 0 || w == HH - 1)) g_bd[bc++] = i;
        }
    }
    if (tid < LL) {
        double di = sdd[tid], ai = saa[tid];
        int rank = 0;
        for (int j = 0; j < LL; j++) {
            double dj = sdd[j], aj = saa[j];
            bool before = (dj > di) ||
                          (dj == di && (aj < ai || (aj == ai && j < tid)));
            rank += before ? 1 : 0;
        }
        g_ra[rank] = tid;
    }
}

// ---------------- im2col for patch embedding ----------------
__global__ void im2col_kernel(const float* __restrict__ x) {
    int idx = blockIdx.x * blockDim.x + threadIdx.x;
    if (idx >= MROWS * EMBED) return;
    int m = idx / EMBED;
    int k = idx % EMBED;
    int b = m / LL, l = m % LL;
    int ph = l / HH, pw = l % HH;
    int c = k / 256, rem = k % 256;
    int i = rem / 16, j = rem % 16;
    g_col[idx] = x[(((size_t)(b * 3 + c) * 224) + (ph * 16 + i)) * 224 + (pw * 16 + j)];
}

// ---------------- add pos_embed + abcde projection into xe ----------------
__global__ void add_pos_ab_kernel(const float* __restrict__ pos_embed,
                                  const float* __restrict__ abcde_features,
                                  const float* __restrict__ abcde_w,
                                  const float* __restrict__ abcde_b)
{
    int idx = blockIdx.x * blockDim.x + threadIdx.x;
    if (idx >= MROWS * EMBED) return;
    int m = idx / EMBED;
    int e = idx % EMBED;
    int b = m / LL;
    float ab = abcde_b[e];
#pragma unroll
    for (int k = 0; k < 5; k++)
        ab += abcde_features[b * 5 + k] * abcde_w[e * 5 + k];
    int l = m % LL;
    g_xe[idx] += pos_embed[l * EMBED + e] + ab;
}

// ---------------- gather 4 orderings into xm ----------------
__global__ void gather_kernel() {
    int idx = blockIdx.x * blockDim.x + threadIdx.x;
    if (idx >= MROWS * DIMM) return;
    int m = idx / DIMM;
    int c = idx % DIMM;
    int b = m / LL, l = m % LL;
    int s = c / EMBED, e = c % EMBED;
    int src_l = (s == 0) ? g_sp[l] : (s == 1) ? g_ra[l] : (s == 2) ? g_bd[l] : l;
    g_xm[idx] = g_xe[((size_t)(b * LL + src_l)) * EMBED + e];
}

// ---------------- layernorm (generic width) ----------------
__global__ void ln_kernel(const float* __restrict__ in, float* __restrict__ out,
                          const float* __restrict__ w, const float* __restrict__ b,
                          int width)
{
    __shared__ float red[256];
    __shared__ float s_mean, s_rstd;
    const int row = blockIdx.x;
    const float* x = in + (size_t)row * width;
    float s = 0.0f;
    for (int j = threadIdx.x; j < width; j += 256) s += x[j];
    red[threadIdx.x] = s; __syncthreads();
    for (int off = 128; off > 0; off >>= 1) {
        if (threadIdx.x < off) red[threadIdx.x] += red[threadIdx.x + off];
        __syncthreads();
    }
    if (threadIdx.x == 0) s_mean = red[0] / (float)width;
    __syncthreads();
    float m = s_mean;
    float vs = 0.0f;
    for (int j = threadIdx.x; j < width; j += 256) {
        float d = x[j] - m; vs += d * d;
    }
    red[threadIdx.x] = vs; __syncthreads();
    for (int off = 128; off > 0; off >>= 1) {
        if (threadIdx.x < off) red[threadIdx.x] += red[threadIdx.x + off];
        __syncthreads();
    }
    if (threadIdx.x == 0) s_rstd = rsqrtf(red[0] / (float)width + 1e-5f);
    __syncthreads();
    float r = s_rstd;
    float* o = out + (size_t)row * width;
    for (int j = threadIdx.x; j < width; j += 256)
        o[j] = (x[j] - m) * r * w[j] + b[j];
}

// ---------------- causal depthwise conv (4 taps) + bias + silu ----------------
__global__ void conv_silu_kernel(const float* __restrict__ conv_w,
                                 const float* __restrict__ conv_b)
{
    int idx = blockIdx.x * blockDim.x + threadIdx.x;
    if (idx >= MROWS * DINN) return;
    int row = idx / DINN;
    int d   = idx % DINN;
    int b = row / LL, t = row % LL;
    float acc = conv_b[d];
#pragma unroll
    for (int j = 0; j < DCONV; j++) {
        int tt = t - (DCONV - 1) + j;
        if (tt >= 0)
            acc += conv_w[d * DCONV + j] * g_xr[((size_t)(b * LL + tt)) * (2 * DINN) + d];
    }
    g_xs[idx] = acc * sigmoidf_(acc);
}

// ---------------- selective scan: one thread per (b, d, n) ----------------
__global__ void scan_kernel(const float* __restrict__ A_log,
                            const float* __restrict__ D_param)
{
    const int g = blockIdx.x * blockDim.x + threadIdx.x;
    const int n  = g & 15;
    const int dg = g >> 4;
    const int d  = dg % DINN;
    const int b  = dg / DINN;

    const float Alog2 = -expf(A_log[d * DSTt + n]) * 1.4426950408889634f;
    const float Dd = D_param[d];

    float st = 0.0f;
#pragma unroll 1
    for (int t = 0; t < LL; t++) {
        const size_t row = (size_t)(b * LL + t);
        const float dtv = g_dt[row * DINN + d];
        const float xv  = g_xs[row * DINN + d];
        const float Bv  = g_dbl[row * XPROJ_N + DTRr + n];
        const float Cv  = g_dbl[row * XPROJ_N + DTRr + DSTt + n];
        st = st * exp2f(dtv * Alog2) + dtv * Bv * xv;
        float p = st * Cv;
        p += __shfl_xor_sync(0xffffffffu, p, 1, 16);
        p += __shfl_xor_sync(0xffffffffu, p, 2, 16);
        p += __shfl_xor_sync(0xffffffffu, p, 4, 16);
        p += __shfl_xor_sync(0xffffffffu, p, 8, 16);
        if (n == 0) {
            float res = g_xr[row * (2 * DINN) + DINN + d];
            float y = (p + xv * Dd) * (res * sigmoidf_(res));
            g_y[row * DINN + d] = y;
        }
    }
}

// ---------------- final mean over L ----------------
__global__ void mean_kernel(float* __restrict__ out) {
    int idx = blockIdx.x * blockDim.x + threadIdx.x;
    if (idx >= BATCH * EMBED) return;
    int b = idx / EMBED, e = idx % EMBED;
    float s = 0.0f;
    for (int l = 0; l < LL; l++)
        s += g_xp[((size_t)(b * LL + l)) * EMBED + e];
    out[idx] = s / (float)LL;
}

// ---------------- launch ----------------
static inline void launch_gemm(const float* A, int lda, const float* B, float* C,
                               int M, int N, int K, const float* bias, int act, int beta)
{
    dim3 grid((N + TNt - 1) / TNt, (M + TMt - 1) / TMt);
    tc_gemm_nt<<<grid, 256, SMEMSZ>>>(A, lda, B, C, M, N, K, bias, act, beta);
}

extern "C" void kernel_launch(void* const* d_in, const int* in_sizes, int n_in,
                              void* d_out, int out_size)
{
    const bool dictOrder = (in_sizes[14] == 2 * DINN * DSTt);

    const float* x          = (const float*)d_in[0];
    const float* abcde_feat = (const float*)d_in[1];
    const float* patch_w    = (const float*)d_in[2];
    const float* patch_b    = (const float*)d_in[3];
    const float* pos_embed  = (const float*)d_in[4];
    const float* abcde_w    = (const float*)d_in[5];
    const float* abcde_b    = (const float*)d_in[6];
    const float* ln_w       = (const float*)d_in[7];
    const float* ln_b       = (const float*)d_in[8];
    const float* in_proj_w  = (const float*)d_in[9];
    const float* conv_w     = (const float*)d_in[10];
    const float* conv_b     = (const float*)d_in[11];
    const float* x_proj_w   = (const float*)d_in[12];
    const float* dt_proj_w  = (const float*)d_in[13];
    const float* dt_proj_b  = dictOrder ? (const float*)d_in[21] : (const float*)d_in[14];
    const float* A_log      = dictOrder ? (const float*)d_in[14] : (const float*)d_in[15];
    const float* D_param    = dictOrder ? (const float*)d_in[15] : (const float*)d_in[16];
    const float* out_proj_w = dictOrder ? (const float*)d_in[16] : (const float*)d_in[17];
    const float* proj_w     = dictOrder ? (const float*)d_in[17] : (const float*)d_in[18];
    const float* proj_b     = dictOrder ? (const float*)d_in[18] : (const float*)d_in[19];
    const float* norm_w     = dictOrder ? (const float*)d_in[19] : (const float*)d_in[20];
    const float* norm_b     = dictOrder ? (const float*)d_in[20] : (const float*)d_in[21];

    float* out = (float*)d_out;

    float* p_col; cudaGetSymbolAddress((void**)&p_col, g_col);
    float* p_xm;  cudaGetSymbolAddress((void**)&p_xm,  g_xm);
    float* p_xln; cudaGetSymbolAddress((void**)&p_xln, g_xln);
    float* p_xr;  cudaGetSymbolAddress((void**)&p_xr,  g_xr);
    float* p_xs;  cudaGetSymbolAddress((void**)&p_xs,  g_xs);
    float* p_dbl; cudaGetSymbolAddress((void**)&p_dbl, g_dbl);
    float* p_dt;  cudaGetSymbolAddress((void**)&p_dt,  g_dt);
    float* p_y;   cudaGetSymbolAddress((void**)&p_y,   g_y);
    float* p_xe;  cudaGetSymbolAddress((void**)&p_xe,  g_xe);
    float* p_xp;  cudaGetSymbolAddress((void**)&p_xp,  g_xp);

    cudaFuncSetAttribute(tc_gemm_nt, cudaFuncAttributeMaxDynamicSharedMemorySize, SMEMSZ);

    // 1. index tables
    compute_indices_kernel<<<1, 256>>>();

    // 2. patch embedding: im2col + GEMM(+bias)
    im2col_kernel<<<(MROWS * EMBED + 255) / 256, 256>>>(x);
    launch_gemm(p_col, EMBED, patch_w, p_xe, MROWS, EMBED, EMBED, patch_b, 0, 0);
    add_pos_ab_kernel<<<(MROWS * EMBED + 255) / 256, 256>>>(pos_embed, abcde_feat, abcde_w, abcde_b);
    gather_kernel<<<(MROWS * DIMM + 255) / 256, 256>>>();

    // 3. mamba layers
    for (int l = 0; l < 2; l++) {
        const float* w_in  = in_proj_w  + (size_t)l * 2 * DINN * DIMM;
        const float* w_cv  = conv_w     + (size_t)l * DINN * DCONV;
        const float* b_cv  = conv_b     + (size_t)l * DINN;
        const float* w_xp  = x_proj_w   + (size_t)l * XPROJ_N * DINN;
        const float* w_dt  = dt_proj_w  + (size_t)l * DINN * DTRr;
        const float* b_dt  = dt_proj_b  + (size_t)l * DINN;
        const float* w_out = out_proj_w + (size_t)l * DIMM * DINN;
        const float* Al    = A_log      + (size_t)l * DINN * DSTt;
        const float* Dl    = D_param    + (size_t)l * DINN;

        ln_kernel<<<MROWS, 256>>>(p_xm, p_xln, ln_w + l * DIMM, ln_b + l * DIMM, DIMM);

        // in_proj: [392,3072] x [12288,3072]^T -> [392,12288]
        launch_gemm(p_xln, DIMM, w_in, p_xr, MROWS, 2 * DINN, DIMM, nullptr, 0, 0);

        conv_silu_kernel<<<(MROWS * DINN + 255) / 256, 256>>>(w_cv, b_cv);

        // x_proj: [392,6144] x [224,6144]^T -> [392,224]
        launch_gemm(p_xs, DINN, w_xp, p_dbl, MROWS, XPROJ_N, DINN, nullptr, 0, 0);

        // dt_proj + bias + softplus: [392,192] x [6144,192]^T -> [392,6144]
        launch_gemm(p_dbl, XPROJ_N, w_dt, p_dt, MROWS, DINN, DTRr, b_dt, 1, 0);

        scan_kernel<<<(BATCH * DINN * DSTt) / 256, 256>>>(Al, Dl);

        // out_proj with residual accumulate into xm
        launch_gemm(p_y, DINN, w_out, p_xm, MROWS, DIMM, DINN, nullptr, 0, 1);
    }

    // 4. final projection + LN + mean
    launch_gemm(p_xm, DIMM, proj_w, p_xp, MROWS, EMBED, DIMM, proj_b, 0, 0);
    ln_kernel<<<MROWS, 256>>>(p_xp, p_xp, norm_w, norm_b, EMBED);
    mean_kernel<<<(BATCH * EMBED + 255) / 256, 256>>>(out);

    (void)n_in; (void)out_size;
}

// round 8
// speedup vs baseline: 2.1096x; 1.0940x over previous
#include <cuda_runtime.h>
#include <cuda_fp16.h>
#include <math.h>
#include <stdint.h>

// ---------------- problem constants ----------------
#define HH      14
#define LL      196            // H*W
#define EMBED   768
#define DIMM    3072           // 4*EMBED
#define DINN    6144           // 2*DIM
#define DTRr    192
#define DSTt    16
#define DCONV   4
#define BATCH   2
#define MROWS   392            // BATCH*LL
#define XPROJ_N 224            // DTR + 2*DST

// ---------------- scratch (device globals; no allocations) ----------------
__device__ float g_col[MROWS * EMBED];
__device__ float g_xe [MROWS * EMBED];
__device__ float g_xm [MROWS * DIMM];
__device__ float g_xln[MROWS * DIMM];
__device__ float g_xr [MROWS * 2 * DINN];
__device__ float g_xs [MROWS * DINN];
__device__ float g_dbl[MROWS * XPROJ_N];
__device__ float g_dt [MROWS * DINN];
__device__ float g_y  [MROWS * DINN];
__device__ float g_xp [MROWS * EMBED];
__device__ int   g_sp[LL];
__device__ int   g_ra[LL];
__device__ int   g_bd[LL];

// ---------------- helpers ----------------
__device__ __forceinline__ float sigmoidf_(float v) { return 1.0f / (1.0f + expf(-v)); }
__device__ __forceinline__ float softplusf_(float v) {
    return v > 0.0f ? v + log1pf(expf(-v)) : log1pf(expf(v));
}
__device__ __forceinline__ void mma_f16(float* c, const uint32_t* a, const uint32_t* b) {
    asm volatile(
        "mma.sync.aligned.m16n8k16.row.col.f32.f16.f16.f32 "
        "{%0,%1,%2,%3}, {%4,%5,%6,%7}, {%8,%9}, {%0,%1,%2,%3};"
        : "+f"(c[0]), "+f"(c[1]), "+f"(c[2]), "+f"(c[3])
        : "r"(a[0]), "r"(a[1]), "r"(a[2]), "r"(a[3]), "r"(b[0]), "r"(b[1]));
}
__device__ __forceinline__ void ldsm4(uint32_t& r0, uint32_t& r1, uint32_t& r2, uint32_t& r3,
                                      uint32_t addr) {
    asm volatile("ldmatrix.sync.aligned.m8n8.x4.shared.b16 {%0,%1,%2,%3}, [%4];"
                 : "=r"(r0), "=r"(r1), "=r"(r2), "=r"(r3) : "r"(addr));
}

// ================= tensor-core GEMM (mma.sync fp16): C[M,N] = A[M,K]*B[N,K]^T =================
// tile 128x128, k16 double-buffered stages. 256 threads = 8 warps (2M x 4N), warp tile 64x32.
// inputs converted fp32->fp16 in the loader; fp32 accumulate; fused bias/softplus/residual.
#define TMt 128
#define TNt 128
#define HPITCH 24                         // halves per row (48B, conflict-free for ldmatrix)
#define ATILE_B (TMt * HPITCH * 2)        // 6144 bytes per operand per stage
#define STAGE_B (2 * ATILE_B)             // 12288
#define SMEMSZ  (2 * STAGE_B)             // 24576

__global__ __launch_bounds__(256, 2)
void tc_gemm_nt(const float* __restrict__ A, int lda,
                const float* __restrict__ B,
                float* __restrict__ C,
                int M, int N, int K,
                const float* __restrict__ bias,
                int act, int beta)
{
    extern __shared__ char smem[];
    const uint32_t sbase = (uint32_t)__cvta_generic_to_shared(smem);
    const int tid  = threadIdx.x;
    const int wid  = tid >> 5;
    const int lane = tid & 31;
    const int g = lane >> 2;              // group 0..7
    const int t = lane & 3;
    const int bm0 = blockIdx.y * TMt;
    const int bn0 = blockIdx.x * TNt;
    const int wm0 = (wid >> 2) * 64;      // warp M offset
    const int wn0 = (wid & 3) * 32;       // warp N offset

    // ldmatrix lane-address offsets (bytes, relative to operand buffer base)
    const int q  = lane >> 3;             // 0..3
    const int ri = lane & 7;
    uint32_t aoff[4], boff[2];
#pragma unroll
    for (int mi = 0; mi < 4; mi++)
        aoff[mi] = (uint32_t)(((wm0 + mi * 16 + (q & 1) * 8 + ri) * HPITCH + (q >> 1) * 8) * 2);
#pragma unroll
    for (int nj = 0; nj < 2; nj++)
        boff[nj] = (uint32_t)(((wn0 + nj * 16 + (q >> 1) * 8 + ri) * HPITCH + (q & 1) * 8) * 2);

    // loader mapping: 2 threads per row, 8 halves (8 floats) each
    const int lrow = tid >> 1;            // 0..127
    const int lk8  = (tid & 1) * 8;       // k offset within stage
    int ar = bm0 + lrow; if (ar > M - 1) ar = M - 1;
    int br = bn0 + lrow; if (br > N - 1) br = N - 1;
    const float* pa = A + (size_t)ar * lda + lk8;
    const float* pb = B + (size_t)br * K + lk8;
    const uint32_t soff = (uint32_t)((lrow * HPITCH + lk8) * 2);

    float4 ra0, ra1, rb0, rb1;
    auto ldg_stage = [&](int k0) {
        ra0 = *reinterpret_cast<const float4*>(pa + k0);
        ra1 = *reinterpret_cast<const float4*>(pa + k0 + 4);
        rb0 = *reinterpret_cast<const float4*>(pb + k0);
        rb1 = *reinterpret_cast<const float4*>(pb + k0 + 4);
    };
    auto sts_stage = [&](int buf) {
        __half2 ha[4], hb[4];
        ha[0] = __floats2half2_rn(ra0.x, ra0.y); ha[1] = __floats2half2_rn(ra0.z, ra0.w);
        ha[2] = __floats2half2_rn(ra1.x, ra1.y); ha[3] = __floats2half2_rn(ra1.z, ra1.w);
        hb[0] = __floats2half2_rn(rb0.x, rb0.y); hb[1] = __floats2half2_rn(rb0.z, rb0.w);
        hb[2] = __floats2half2_rn(rb1.x, rb1.y); hb[3] = __floats2half2_rn(rb1.z, rb1.w);
        char* base = smem + buf * STAGE_B;
        *reinterpret_cast<uint4*>(base + soff)           = *reinterpret_cast<uint4*>(ha);
        *reinterpret_cast<uint4*>(base + ATILE_B + soff) = *reinterpret_cast<uint4*>(hb);
    };

    float c[4][4][4];
#pragma unroll
    for (int mi = 0; mi < 4; mi++)
#pragma unroll
        for (int ni = 0; ni < 4; ni++)
#pragma unroll
            for (int r = 0; r < 4; r++) c[mi][ni][r] = 0.0f;

    const int ns = K >> 4;                // k16 stages
    ldg_stage(0);
    sts_stage(0);
    __syncthreads();

    for (int s = 0; s < ns; s++) {
        const int buf = s & 1;
        if (s + 1 < ns) ldg_stage((s + 1) << 4);

        const uint32_t abase = sbase + buf * STAGE_B;
        const uint32_t bbase = abase + ATILE_B;
        uint32_t a[4][4], b[4][2];
#pragma unroll
        for (int mi = 0; mi < 4; mi++)
            ldsm4(a[mi][0], a[mi][1], a[mi][2], a[mi][3], abase + aoff[mi]);
#pragma unroll
        for (int nj = 0; nj < 2; nj++) {
            uint32_t r0, r1, r2, r3;
            ldsm4(r0, r1, r2, r3, bbase + boff[nj]);
            b[2 * nj][0] = r0; b[2 * nj][1] = r1;
            b[2 * nj + 1][0] = r2; b[2 * nj + 1][1] = r3;
        }
#pragma unroll
        for (int mi = 0; mi < 4; mi++)
#pragma unroll
            for (int ni = 0; ni < 4; ni++)
                mma_f16(c[mi][ni], a[mi], b[ni]);

        __syncthreads();
        if (s + 1 < ns) {
            sts_stage(buf ^ 1);
            __syncthreads();
        }
    }

    // epilogue
#pragma unroll
    for (int mi = 0; mi < 4; mi++) {
        const int row0 = bm0 + wm0 + mi * 16 + g;
#pragma unroll
        for (int ni = 0; ni < 4; ni++) {
            const int col0 = bn0 + wn0 + ni * 8 + 2 * t;
#pragma unroll
            for (int r = 0; r < 4; r++) {
                const int row = row0 + ((r >> 1) << 3);
                const int col = col0 + (r & 1);
                if (row < M && col < N) {
                    float v = c[mi][ni][r];
                    if (bias) v += bias[col];
                    if (act == 1) v = softplusf_(v);
                    float* p = C + (size_t)row * N + col;
                    if (beta) *p += v; else *p = v;
                }
            }
        }
    }
}

// ---------------- index tables (replicates numpy double-precision exactly) ----------------
__global__ void compute_indices_kernel() {
    __shared__ double sdd[LL];
    __shared__ double saa[LL];
    __shared__ int    cand[202];
    __shared__ unsigned char seen[LL];
    const int tid = threadIdx.x;
    const double TWO_PI = 2.0 * 3.14159265358979323846;

    if (tid < 202) {
        int r = 0, rem = tid;
        for (;;) {
            int c = (2 * r > 8) ? 2 * r : 8;
            if (rem < c) break;
            rem -= c; r++;
        }
        int nang = (2 * r > 8) ? 2 * r : 8;
        double step = TWO_PI / (double)nang;
        double ang = (double)rem * step;
        double hh = 7.0 + (double)r * cos(ang);
        double ww = 7.0 + (double)r * sin(ang);
        int h = (int)hh;
        int w = (int)ww;
        cand[tid] = (h >= 0 && h < HH && w >= 0 && w < HH) ? (h * HH + w) : -1;
    }
    if (tid < LL) {
        seen[tid] = 0;
        int h = tid / HH, w = tid % HH;
        double dy = (double)(h - 7), dx = (double)(w - 7);
        sdd[tid] = sqrt(dy * dy + dx * dx);
        saa[tid] = atan2(dy, dx);
    }
    __syncthreads();

    if (tid == 0) {
        int cnt = 0;
        for (int i = 0; i < 202; i++) {
            int c = cand[i];
            if (c >= 0 && !seen[c]) { seen[c] = 1; g_sp[cnt++] = c; }
        }
        for (int i = 0; i < LL; i++)
            if (!seen[i]) g_sp[cnt++] = i;
        int bc = 0;
        for (int i = 0; i < LL; i++) {
            int h = i / HH, w = i % HH;
            if (h == 0 || h == HH - 1 || w == 0 || w == HH - 1) g_bd[bc++] = i;
        }
        for (int i = 0; i < LL; i++) {
            int h = i / HH, w = i % HH;
            if (!(h == 0 || h == HH - 1 || w == 0 || w == HH - 1)) g_bd[bc++] = i;
        }
    }
    if (tid < LL) {
        double di = sdd[tid], ai = saa[tid];
        int rank = 0;
        for (int j = 0; j < LL; j++) {
            double dj = sdd[j], aj = saa[j];
            bool before = (dj > di) ||
                          (dj == di && (aj < ai || (aj == ai && j < tid)));
            rank += before ? 1 : 0;
        }
        g_ra[rank] = tid;
    }
}

// ---------------- im2col for patch embedding ----------------
__global__ void im2col_kernel(const float* __restrict__ x) {
    int idx = blockIdx.x * blockDim.x + threadIdx.x;
    if (idx >= MROWS * EMBED) return;
    int m = idx / EMBED;
    int k = idx % EMBED;
    int b = m / LL, l = m % LL;
    int ph = l / HH, pw = l % HH;
    int c = k / 256, rem = k % 256;
    int i = rem / 16, j = rem % 16;
    g_col[idx] = x[(((size_t)(b * 3 + c) * 224) + (ph * 16 + i)) * 224 + (pw * 16 + j)];
}

// ---------------- add pos_embed + abcde projection into xe ----------------
__global__ void add_pos_ab_kernel(const float* __restrict__ pos_embed,
                                  const float* __restrict__ abcde_features,
                                  const float* __restrict__ abcde_w,
                                  const float* __restrict__ abcde_b)
{
    int idx = blockIdx.x * blockDim.x + threadIdx.x;
    if (idx >= MROWS * EMBED) return;
    int m = idx / EMBED;
    int e = idx % EMBED;
    int b = m / LL;
    float ab = abcde_b[e];
#pragma unroll
    for (int k = 0; k < 5; k++)
        ab += abcde_features[b * 5 + k] * abcde_w[e * 5 + k];
    int l = m % LL;
    g_xe[idx] += pos_embed[l * EMBED + e] + ab;
}

// ---------------- gather 4 orderings into xm ----------------
__global__ void gather_kernel() {
    int idx = blockIdx.x * blockDim.x + threadIdx.x;
    if (idx >= MROWS * DIMM) return;
    int m = idx / DIMM;
    int c = idx % DIMM;
    int b = m / LL, l = m % LL;
    int s = c / EMBED, e = c % EMBED;
    int src_l = (s == 0) ? g_sp[l] : (s == 1) ? g_ra[l] : (s == 2) ? g_bd[l] : l;
    g_xm[idx] = g_xe[((size_t)(b * LL + src_l)) * EMBED + e];
}

// ---------------- layernorm (generic width) ----------------
__global__ void ln_kernel(const float* __restrict__ in, float* __restrict__ out,
                          const float* __restrict__ w, const float* __restrict__ b,
                          int width)
{
    __shared__ float red[256];
    __shared__ float s_mean, s_rstd;
    const int row = blockIdx.x;
    const float* x = in + (size_t)row * width;
    float s = 0.0f;
    for (int j = threadIdx.x; j < width; j += 256) s += x[j];
    red[threadIdx.x] = s; __syncthreads();
    for (int off = 128; off > 0; off >>= 1) {
        if (threadIdx.x < off) red[threadIdx.x] += red[threadIdx.x + off];
        __syncthreads();
    }
    if (threadIdx.x == 0) s_mean = red[0] / (float)width;
    __syncthreads();
    float m = s_mean;
    float vs = 0.0f;
    for (int j = threadIdx.x; j < width; j += 256) {
        float d = x[j] - m; vs += d * d;
    }
    red[threadIdx.x] = vs; __syncthreads();
    for (int off = 128; off > 0; off >>= 1) {
        if (threadIdx.x < off) red[threadIdx.x] += red[threadIdx.x + off];
        __syncthreads();
    }
    if (threadIdx.x == 0) s_rstd = rsqrtf(red[0] / (float)width + 1e-5f);
    __syncthreads();
    float r = s_rstd;
    float* o = out + (size_t)row * width;
    for (int j = threadIdx.x; j < width; j += 256)
        o[j] = (x[j] - m) * r * w[j] + b[j];
}

// ---------------- causal depthwise conv (4 taps) + bias + silu ----------------
__global__ void conv_silu_kernel(const float* __restrict__ conv_w,
                                 const float* __restrict__ conv_b)
{
    int idx = blockIdx.x * blockDim.x + threadIdx.x;
    if (idx >= MROWS * DINN) return;
    int row = idx / DINN;
    int d   = idx % DINN;
    int b = row / LL, t = row % LL;
    float acc = conv_b[d];
#pragma unroll
    for (int j = 0; j < DCONV; j++) {
        int tt = t - (DCONV - 1) + j;
        if (tt >= 0)
            acc += conv_w[d * DCONV + j] * g_xr[((size_t)(b * LL + tt)) * (2 * DINN) + d];
    }
    g_xs[idx] = acc * sigmoidf_(acc);
}

// ---------------- selective scan: one thread per (b, d, n) ----------------
__global__ void scan_kernel(const float* __restrict__ A_log,
                            const float* __restrict__ D_param)
{
    const int g = blockIdx.x * blockDim.x + threadIdx.x;
    const int n  = g & 15;
    const int dg = g >> 4;
    const int d  = dg % DINN;
    const int b  = dg / DINN;

    const float Alog2 = -expf(A_log[d * DSTt + n]) * 1.4426950408889634f;
    const float Dd = D_param[d];

    float st = 0.0f;
#pragma unroll 1
    for (int t = 0; t < LL; t++) {
        const size_t row = (size_t)(b * LL + t);
        const float dtv = g_dt[row * DINN + d];
        const float xv  = g_xs[row * DINN + d];
        const float Bv  = g_dbl[row * XPROJ_N + DTRr + n];
        const float Cv  = g_dbl[row * XPROJ_N + DTRr + DSTt + n];
        st = st * exp2f(dtv * Alog2) + dtv * Bv * xv;
        float p = st * Cv;
        p += __shfl_xor_sync(0xffffffffu, p, 1, 16);
        p += __shfl_xor_sync(0xffffffffu, p, 2, 16);
        p += __shfl_xor_sync(0xffffffffu, p, 4, 16);
        p += __shfl_xor_sync(0xffffffffu, p, 8, 16);
        if (n == 0) {
            float res = g_xr[row * (2 * DINN) + DINN + d];
            float y = (p + xv * Dd) * (res * sigmoidf_(res));
            g_y[row * DINN + d] = y;
        }
    }
}

// ---------------- final mean over L ----------------
__global__ void mean_kernel(float* __restrict__ out) {
    int idx = blockIdx.x * blockDim.x + threadIdx.x;
    if (idx >= BATCH * EMBED) return;
    int b = idx / EMBED, e = idx % EMBED;
    float s = 0.0f;
    for (int l = 0; l < LL; l++)
        s += g_xp[((size_t)(b * LL + l)) * EMBED + e];
    out[idx] = s / (float)LL;
}

// ---------------- launch ----------------
static inline void launch_gemm(const float* A, int lda, const float* B, float* C,
                               int M, int N, int K, const float* bias, int act, int beta)
{
    dim3 grid((N + TNt - 1) / TNt, (M + TMt - 1) / TMt);
    tc_gemm_nt<<<grid, 256, SMEMSZ>>>(A, lda, B, C, M, N, K, bias, act, beta);
}

extern "C" void kernel_launch(void* const* d_in, const int* in_sizes, int n_in,
                              void* d_out, int out_size)
{
    const bool dictOrder = (in_sizes[14] == 2 * DINN * DSTt);

    const float* x          = (const float*)d_in[0];
    const float* abcde_feat = (const float*)d_in[1];
    const float* patch_w    = (const float*)d_in[2];
    const float* patch_b    = (const float*)d_in[3];
    const float* pos_embed  = (const float*)d_in[4];
    const float* abcde_w    = (const float*)d_in[5];
    const float* abcde_b    = (const float*)d_in[6];
    const float* ln_w       = (const float*)d_in[7];
    const float* ln_b       = (const float*)d_in[8];
    const float* in_proj_w  = (const float*)d_in[9];
    const float* conv_w     = (const float*)d_in[10];
    const float* conv_b     = (const float*)d_in[11];
    const float* x_proj_w   = (const float*)d_in[12];
    const float* dt_proj_w  = (const float*)d_in[13];
    const float* dt_proj_b  = dictOrder ? (const float*)d_in[21] : (const float*)d_in[14];
    const float* A_log      = dictOrder ? (const float*)d_in[14] : (const float*)d_in[15];
    const float* D_param    = dictOrder ? (const float*)d_in[15] : (const float*)d_in[16];
    const float* out_proj_w = dictOrder ? (const float*)d_in[16] : (const float*)d_in[17];
    const float* proj_w     = dictOrder ? (const float*)d_in[17] : (const float*)d_in[18];
    const float* proj_b     = dictOrder ? (const float*)d_in[18] : (const float*)d_in[19];
    const float* norm_w     = dictOrder ? (const float*)d_in[19] : (const float*)d_in[20];
    const float* norm_b     = dictOrder ? (const float*)d_in[20] : (const float*)d_in[21];

    float* out = (float*)d_out;

    float* p_col; cudaGetSymbolAddress((void**)&p_col, g_col);
    float* p_xm;  cudaGetSymbolAddress((void**)&p_xm,  g_xm);
    float* p_xln; cudaGetSymbolAddress((void**)&p_xln, g_xln);
    float* p_xr;  cudaGetSymbolAddress((void**)&p_xr,  g_xr);
    float* p_xs;  cudaGetSymbolAddress((void**)&p_xs,  g_xs);
    float* p_dbl; cudaGetSymbolAddress((void**)&p_dbl, g_dbl);
    float* p_dt;  cudaGetSymbolAddress((void**)&p_dt,  g_dt);
    float* p_y;   cudaGetSymbolAddress((void**)&p_y,   g_y);
    float* p_xe;  cudaGetSymbolAddress((void**)&p_xe,  g_xe);
    float* p_xp;  cudaGetSymbolAddress((void**)&p_xp,  g_xp);

    cudaFuncSetAttribute(tc_gemm_nt, cudaFuncAttributeMaxDynamicSharedMemorySize, SMEMSZ);

    // 1. index tables
    compute_indices_kernel<<<1, 256>>>();

    // 2. patch embedding: im2col + GEMM(+bias)
    im2col_kernel<<<(MROWS * EMBED + 255) / 256, 256>>>(x);
    launch_gemm(p_col, EMBED, patch_w, p_xe, MROWS, EMBED, EMBED, patch_b, 0, 0);
    add_pos_ab_kernel<<<(MROWS * EMBED + 255) / 256, 256>>>(pos_embed, abcde_feat, abcde_w, abcde_b);
    gather_kernel<<<(MROWS * DIMM + 255) / 256, 256>>>();

    // 3. mamba layers
    for (int l = 0; l < 2; l++) {
        const float* w_in  = in_proj_w  + (size_t)l * 2 * DINN * DIMM;
        const float* w_cv  = conv_w     + (size_t)l * DINN * DCONV;
        const float* b_cv  = conv_b     + (size_t)l * DINN;
        const float* w_xp  = x_proj_w   + (size_t)l * XPROJ_N * DINN;
        const float* w_dt  = dt_proj_w  + (size_t)l * DINN * DTRr;
        const float* b_dt  = dt_proj_b  + (size_t)l * DINN;
        const float* w_out = out_proj_w + (size_t)l * DIMM * DINN;
        const float* Al    = A_log      + (size_t)l * DINN * DSTt;
        const float* Dl    = D_param    + (size_t)l * DINN;

        ln_kernel<<<MROWS, 256>>>(p_xm, p_xln, ln_w + l * DIMM, ln_b + l * DIMM, DIMM);

        // in_proj: [392,3072] x [12288,3072]^T -> [392,12288]
        launch_gemm(p_xln, DIMM, w_in, p_xr, MROWS, 2 * DINN, DIMM, nullptr, 0, 0);

        conv_silu_kernel<<<(MROWS * DINN + 255) / 256, 256>>>(w_cv, b_cv);

        // x_proj: [392,6144] x [224,6144]^T -> [392,224]
        launch_gemm(p_xs, DINN, w_xp, p_dbl, MROWS, XPROJ_N, DINN, nullptr, 0, 0);

        // dt_proj + bias + softplus: [392,192] x [6144,192]^T -> [392,6144]
        launch_gemm(p_dbl, XPROJ_N, w_dt, p_dt, MROWS, DINN, DTRr, b_dt, 1, 0);

        scan_kernel<<<(BATCH * DINN * DSTt) / 256, 256>>>(Al, Dl);

        // out_proj with residual accumulate into xm
        launch_gemm(p_y, DINN, w_out, p_xm, MROWS, DIMM, DINN, nullptr, 0, 1);
    }

    // 4. final projection + LN + mean
    launch_gemm(p_xm, DIMM, proj_w, p_xp, MROWS, EMBED, DIMM, proj_b, 0, 0);
    ln_kernel<<<MROWS, 256>>>(p_xp, p_xp, norm_w, norm_b, EMBED);
    mean_kernel<<<(BATCH * EMBED + 255) / 256, 256>>>(out);

    (void)n_in; (void)out_size;
}

// round 9
// speedup vs baseline: 3.7103x; 1.7588x over previous
#include <cuda_runtime.h>
#include <cuda_fp16.h>
#include <math.h>
#include <stdint.h>

// ---------------- problem constants ----------------
#define HH      14
#define LL      196            // H*W
#define EMBED   768
#define DIMM    3072           // 4*EMBED
#define DINN    6144           // 2*DIM
#define DTRr    192
#define DSTt    16
#define DCONV   4
#define BATCH   2
#define MROWS   392            // BATCH*LL
#define XPROJ_N 224            // DTR + 2*DST

// ---------------- fp32 scratch ----------------
__device__ float g_xe [MROWS * EMBED];
__device__ float g_xm [MROWS * DIMM];
__device__ float g_xr [MROWS * 2 * DINN];
__device__ float g_xs [MROWS * DINN];
__device__ float g_dbl[MROWS * XPROJ_N];
__device__ float g_dt [MROWS * DINN];
__device__ float g_xp [MROWS * EMBED];
__device__ float g_split[8 * MROWS * 768];   // split-K partials (max need)
__device__ int   g_sp[LL];
__device__ int   g_ra[LL];
__device__ int   g_bd[LL];

// ---------------- fp16 mirrors (GEMM operands) ----------------
__device__ __half h_col [MROWS * EMBED];
__device__ __half h_xln [MROWS * DIMM];
__device__ __half h_xs  [MROWS * DINN];
__device__ __half h_dbl [MROWS * XPROJ_N];
__device__ __half h_y   [MROWS * DINN];
__device__ __half h_xm  [MROWS * DIMM];
// fp16 weights
__device__ __half h_patchw[EMBED * EMBED];
__device__ __half h_inw  [2 * 2 * DINN * DIMM];
__device__ __half h_xpw  [2 * XPROJ_N * DINN];
__device__ __half h_dtw  [2 * DINN * DTRr];
__device__ __half h_outw [2 * DIMM * DINN];
__device__ __half h_projw[EMBED * DIMM];

// ---------------- helpers ----------------
__device__ __forceinline__ float sigmoidf_(float v) { return 1.0f / (1.0f + expf(-v)); }
__device__ __forceinline__ float softplusf_(float v) {
    return v > 0.0f ? v + log1pf(expf(-v)) : log1pf(expf(v));
}
__device__ __forceinline__ void mma_f16(float* c, const uint32_t* a, const uint32_t* b) {
    asm volatile(
        "mma.sync.aligned.m16n8k16.row.col.f32.f16.f16.f32 "
        "{%0,%1,%2,%3}, {%4,%5,%6,%7}, {%8,%9}, {%0,%1,%2,%3};"
        : "+f"(c[0]), "+f"(c[1]), "+f"(c[2]), "+f"(c[3])
        : "r"(a[0]), "r"(a[1]), "r"(a[2]), "r"(a[3]), "r"(b[0]), "r"(b[1]));
}
__device__ __forceinline__ void ldsm4(uint32_t& r0, uint32_t& r1, uint32_t& r2, uint32_t& r3,
                                      uint32_t addr) {
    asm volatile("ldmatrix.sync.aligned.m8n8.x4.shared.b16 {%0,%1,%2,%3}, [%4];"
                 : "=r"(r0), "=r"(r1), "=r"(r2), "=r"(r3) : "r"(addr));
}
__device__ __forceinline__ void cp_async16(uint32_t dst, const __half* src) {
    asm volatile("cp.async.ca.shared.global [%0], [%1], 16;"
                 :: "r"(dst), "l"(__cvta_generic_to_global(src)) : "memory");
}
__device__ __forceinline__ void cp_commit() {
    asm volatile("cp.async.commit_group;" ::: "memory");
}
__device__ __forceinline__ void cp_wait2() {
    asm volatile("cp.async.wait_group 2;" ::: "memory");
}

// ================= fp16 tensor-core GEMM, cp.async 4-stage: C[M,N]=A[M,K]*B[N,K]^T =================
// tile 128x128 x k16 stages; 256 threads = 8 warps (2M x 4N), warp tile 64x32.
// split-K via gridDim.z (partials to C + z*M*N; bias/act/beta/Ch only meaningful for z==1 grids).
#define TMt 128
#define TNt 128
#define NST 4
#define HPITCH 24                          // halves per smem row (48B), conflict-free ldmatrix
#define ATILE_B (TMt * HPITCH * 2)         // 6144 B per operand per stage
#define STAGE_B (2 * ATILE_B)              // 12288 B
#define SMEMSZ  (NST * STAGE_B)            // 49152 B

__global__ __launch_bounds__(256, 2)
void tc_gemm_nt(const __half* __restrict__ A, int lda,
                const __half* __restrict__ B,
                float* __restrict__ C, __half* __restrict__ Ch,
                int M, int N, int K,
                const float* __restrict__ bias,
                int act, int beta)
{
    extern __shared__ char smem[];
    const uint32_t sbase = (uint32_t)__cvta_generic_to_shared(smem);
    const int tid  = threadIdx.x;
    const int wid  = tid >> 5;
    const int lane = tid & 31;
    const int g = lane >> 2;
    const int t = lane & 3;
    const int bm0 = blockIdx.y * TMt;
    const int bn0 = blockIdx.x * TNt;
    const int wm0 = (wid >> 2) * 64;
    const int wn0 = (wid & 3) * 32;

    const int kchunk = K / gridDim.z;
    const int koff   = blockIdx.z * kchunk;
    const int ns     = kchunk >> 4;
    C += (size_t)blockIdx.z * M * N;

    // ldmatrix lane offsets (bytes within operand buffer)
    const int q  = lane >> 3;
    const int ri = lane & 7;
    uint32_t aoff[4], boff[2];
#pragma unroll
    for (int mi = 0; mi < 4; mi++)
        aoff[mi] = (uint32_t)(((wm0 + mi * 16 + (q & 1) * 8 + ri) * HPITCH + (q >> 1) * 8) * 2);
#pragma unroll
    for (int nj = 0; nj < 2; nj++)
        boff[nj] = (uint32_t)(((wn0 + nj * 16 + (q >> 1) * 8 + ri) * HPITCH + (q & 1) * 8) * 2);

    // cp.async mapping: 2 threads per row, 8 halves (16B) each
    const int lrow = tid >> 1;
    const int lk8  = (tid & 1) * 8;
    int ar = bm0 + lrow; if (ar > M - 1) ar = M - 1;
    int br = bn0 + lrow; if (br > N - 1) br = N - 1;
    const __half* pa = A + (size_t)ar * lda + koff + lk8;
    const __half* pb = B + (size_t)br * K + koff + lk8;
    const uint32_t soff = (uint32_t)((lrow * HPITCH + lk8) * 2);

    auto issue = [&](int s) {
        const uint32_t base = sbase + (uint32_t)(s % NST) * STAGE_B;
        cp_async16(base + soff, pa + s * 16);
        cp_async16(base + ATILE_B + soff, pb + s * 16);
        cp_commit();
    };

    float c[4][4][4];
#pragma unroll
    for (int mi = 0; mi < 4; mi++)
#pragma unroll
        for (int ni = 0; ni < 4; ni++)
#pragma unroll
            for (int r = 0; r < 4; r++) c[mi][ni][r] = 0.0f;

    // prologue: stages 0..NST-2
#pragma unroll
    for (int s = 0; s < NST - 1; s++) {
        if (s < ns) issue(s); else cp_commit();
    }

    for (int s = 0; s < ns; s++) {
        cp_wait2();
        __syncthreads();
        if (s + NST - 1 < ns) issue(s + NST - 1); else cp_commit();

        const uint32_t abase = sbase + (uint32_t)(s % NST) * STAGE_B;
        const uint32_t bbase = abase + ATILE_B;
        uint32_t a[4][4], b[4][2];
#pragma unroll
        for (int mi = 0; mi < 4; mi++)
            ldsm4(a[mi][0], a[mi][1], a[mi][2], a[mi][3], abase + aoff[mi]);
#pragma unroll
        for (int nj = 0; nj < 2; nj++) {
            uint32_t r0, r1, r2, r3;
            ldsm4(r0, r1, r2, r3, bbase + boff[nj]);
            b[2 * nj][0] = r0; b[2 * nj][1] = r1;
            b[2 * nj + 1][0] = r2; b[2 * nj + 1][1] = r3;
        }
#pragma unroll
        for (int mi = 0; mi < 4; mi++)
#pragma unroll
            for (int ni = 0; ni < 4; ni++)
                mma_f16(c[mi][ni], a[mi], b[ni]);
    }

    // epilogue
#pragma unroll
    for (int mi = 0; mi < 4; mi++) {
        const int row0 = bm0 + wm0 + mi * 16 + g;
#pragma unroll
        for (int ni = 0; ni < 4; ni++) {
            const int col0 = bn0 + wn0 + ni * 8 + 2 * t;
#pragma unroll
            for (int r = 0; r < 4; r++) {
                const int row = row0 + ((r >> 1) << 3);
                const int col = col0 + (r & 1);
                if (row < M && col < N) {
                    float v = c[mi][ni][r];
                    if (bias) v += bias[col];
                    if (act == 1) v = softplusf_(v);
                    float* p = C + (size_t)row * N + col;
                    if (beta) v += *p;
                    *p = v;
                    if (Ch) Ch[(size_t)row * N + col] = __float2half(v);
                }
            }
        }
    }
}

// ---------------- split-K reduce (+bias, + fp16 mirror) ----------------
__global__ void reduce_split_kernel(const float* __restrict__ sp,
                                    float* __restrict__ C, __half* __restrict__ Ch,
                                    const float* __restrict__ bias,
                                    int nsplit, int MN, int N)
{
    int idx = blockIdx.x * blockDim.x + threadIdx.x;
    if (idx >= MN) return;
    float s = 0.0f;
    for (int i = 0; i < nsplit; i++) s += sp[(size_t)i * MN + idx];
    if (bias) s += bias[idx % N];
    C[idx] = s;
    if (Ch) Ch[idx] = __float2half(s);
}

// ---------------- fp32 -> fp16 convert ----------------
__global__ void f2h_kernel(const float* __restrict__ src, __half* __restrict__ dst, int n4)
{
    int idx = blockIdx.x * blockDim.x + threadIdx.x;
    if (idx >= n4) return;
    float4 v = reinterpret_cast<const float4*>(src)[idx];
    __half2* d = reinterpret_cast<__half2*>(dst) + 2 * idx;
    d[0] = __floats2half2_rn(v.x, v.y);
    d[1] = __floats2half2_rn(v.z, v.w);
}

// ---------------- index tables (numpy double-precision exact) ----------------
__global__ void compute_indices_kernel() {
    __shared__ double sdd[LL];
    __shared__ double saa[LL];
    __shared__ int    cand[202];
    __shared__ unsigned char seen[LL];
    const int tid = threadIdx.x;
    const double TWO_PI = 2.0 * 3.14159265358979323846;

    if (tid < 202) {
        int r = 0, rem = tid;
        for (;;) {
            int c = (2 * r > 8) ? 2 * r : 8;
            if (rem < c) break;
            rem -= c; r++;
        }
        int nang = (2 * r > 8) ? 2 * r : 8;
        double step = TWO_PI / (double)nang;
        double ang = (double)rem * step;
        double hh = 7.0 + (double)r * cos(ang);
        double ww = 7.0 + (double)r * sin(ang);
        int h = (int)hh;
        int w = (int)ww;
        cand[tid] = (h >= 0 && h < HH && w >= 0 && w < HH) ? (h * HH + w) : -1;
    }
    if (tid < LL) {
        seen[tid] = 0;
        int h = tid / HH, w = tid % HH;
        double dy = (double)(h - 7), dx = (double)(w - 7);
        sdd[tid] = sqrt(dy * dy + dx * dx);
        saa[tid] = atan2(dy, dx);
    }
    __syncthreads();

    if (tid == 0) {
        int cnt = 0;
        for (int i = 0; i < 202; i++) {
            int c = cand[i];
            if (c >= 0 && !seen[c]) { seen[c] = 1; g_sp[cnt++] = c; }
        }
        for (int i = 0; i < LL; i++)
            if (!seen[i]) g_sp[cnt++] = i;
        int bc = 0;
        for (int i = 0; i < LL; i++) {
            int h = i / HH, w = i % HH;
            if (h == 0 || h == HH - 1 || w == 0 || w == HH - 1) g_bd[bc++] = i;
        }
        for (int i = 0; i < LL; i++) {
            int h = i / HH, w = i % HH;
            if (!(h == 0 || h == HH - 1 || w == 0 || w == HH - 1)) g_bd[bc++] = i;
        }
    }
    if (tid < LL) {
        double di = sdd[tid], ai = saa[tid];
        int rank = 0;
        for (int j = 0; j < LL; j++) {
            double dj = sdd[j], aj = saa[j];
            bool before = (dj > di) ||
                          (dj == di && (aj < ai || (aj == ai && j < tid)));
            rank += before ? 1 : 0;
        }
        g_ra[rank] = tid;
    }
}

// ---------------- im2col (fp16 out) ----------------
__global__ void im2col_kernel(const float* __restrict__ x) {
    int idx = blockIdx.x * blockDim.x + threadIdx.x;
    if (idx >= MROWS * EMBED) return;
    int m = idx / EMBED;
    int k = idx % EMBED;
    int b = m / LL, l = m % LL;
    int ph = l / HH, pw = l % HH;
    int c = k / 256, rem = k % 256;
    int i = rem / 16, j = rem % 16;
    h_col[idx] = __float2half(
        x[(((size_t)(b * 3 + c) * 224) + (ph * 16 + i)) * 224 + (pw * 16 + j)]);
}

// ---------------- add pos_embed + abcde projection ----------------
__global__ void add_pos_ab_kernel(const float* __restrict__ pos_embed,
                                  const float* __restrict__ abcde_features,
                                  const float* __restrict__ abcde_w,
                                  const float* __restrict__ abcde_b)
{
    int idx = blockIdx.x * blockDim.x + threadIdx.x;
    if (idx >= MROWS * EMBED) return;
    int m = idx / EMBED;
    int e = idx % EMBED;
    int b = m / LL;
    float ab = abcde_b[e];
#pragma unroll
    for (int k = 0; k < 5; k++)
        ab += abcde_features[b * 5 + k] * abcde_w[e * 5 + k];
    int l = m % LL;
    g_xe[idx] += pos_embed[l * EMBED + e] + ab;
}

// ---------------- gather 4 orderings into xm ----------------
__global__ void gather_kernel() {
    int idx = blockIdx.x * blockDim.x + threadIdx.x;
    if (idx >= MROWS * DIMM) return;
    int m = idx / DIMM;
    int c = idx % DIMM;
    int b = m / LL, l = m % LL;
    int s = c / EMBED, e = c % EMBED;
    int src_l = (s == 0) ? g_sp[l] : (s == 1) ? g_ra[l] : (s == 2) ? g_bd[l] : l;
    g_xm[idx] = g_xe[((size_t)(b * LL + src_l)) * EMBED + e];
}

// ---------------- layernorm (fp32 in; optional fp32 / fp16 outs) ----------------
__global__ void ln_kernel(const float* __restrict__ in,
                          float* __restrict__ out_f, __half* __restrict__ out_h,
                          const float* __restrict__ w, const float* __restrict__ b,
                          int width)
{
    __shared__ float red[256];
    __shared__ float s_mean, s_rstd;
    const int row = blockIdx.x;
    const float* x = in + (size_t)row * width;
    float s = 0.0f;
    for (int j = threadIdx.x; j < width; j += 256) s += x[j];
    red[threadIdx.x] = s; __syncthreads();
    for (int off = 128; off > 0; off >>= 1) {
        if (threadIdx.x < off) red[threadIdx.x] += red[threadIdx.x + off];
        __syncthreads();
    }
    if (threadIdx.x == 0) s_mean = red[0] / (float)width;
    __syncthreads();
    float m = s_mean;
    float vs = 0.0f;
    for (int j = threadIdx.x; j < width; j += 256) {
        float d = x[j] - m; vs += d * d;
    }
    red[threadIdx.x] = vs; __syncthreads();
    for (int off = 128; off > 0; off >>= 1) {
        if (threadIdx.x < off) red[threadIdx.x] += red[threadIdx.x + off];
        __syncthreads();
    }
    if (threadIdx.x == 0) s_rstd = rsqrtf(red[0] / (float)width + 1e-5f);
    __syncthreads();
    float r = s_rstd;
    for (int j = threadIdx.x; j < width; j += 256) {
        float v = (x[j] - m) * r * w[j] + b[j];
        if (out_f) out_f[(size_t)row * width + j] = v;
        if (out_h) out_h[(size_t)row * width + j] = __float2half(v);
    }
}

// ---------------- causal depthwise conv + bias + silu (fp32 + fp16 out) ----------------
__global__ void conv_silu_kernel(const float* __restrict__ conv_w,
                                 const float* __restrict__ conv_b)
{
    int idx = blockIdx.x * blockDim.x + threadIdx.x;
    if (idx >= MROWS * DINN) return;
    int row = idx / DINN;
    int d   = idx % DINN;
    int b = row / LL, t = row % LL;
    float acc = conv_b[d];
#pragma unroll
    for (int j = 0; j < DCONV; j++) {
        int tt = t - (DCONV - 1) + j;
        if (tt >= 0)
            acc += conv_w[d * DCONV + j] * g_xr[((size_t)(b * LL + tt)) * (2 * DINN) + d];
    }
    float v = acc * sigmoidf_(acc);
    g_xs[idx] = v;
    h_xs[idx] = __float2half(v);
}

// ---------------- selective scan (fp16 y out) ----------------
__global__ void scan_kernel(const float* __restrict__ A_log,
                            const float* __restrict__ D_param)
{
    const int g = blockIdx.x * blockDim.x + threadIdx.x;
    const int n  = g & 15;
    const int dg = g >> 4;
    const int d  = dg % DINN;
    const int b  = dg / DINN;

    const float Alog2 = -expf(A_log[d * DSTt + n]) * 1.4426950408889634f;
    const float Dd = D_param[d];

    float st = 0.0f;
#pragma unroll 1
    for (int t = 0; t < LL; t++) {
        const size_t row = (size_t)(b * LL + t);
        const float dtv = g_dt[row * DINN + d];
        const float xv  = g_xs[row * DINN + d];
        const float Bv  = g_dbl[row * XPROJ_N + DTRr + n];
        const float Cv  = g_dbl[row * XPROJ_N + DTRr + DSTt + n];
        st = st * exp2f(dtv * Alog2) + dtv * Bv * xv;
        float p = st * Cv;
        p += __shfl_xor_sync(0xffffffffu, p, 1, 16);
        p += __shfl_xor_sync(0xffffffffu, p, 2, 16);
        p += __shfl_xor_sync(0xffffffffu, p, 4, 16);
        p += __shfl_xor_sync(0xffffffffu, p, 8, 16);
        if (n == 0) {
            float res = g_xr[row * (2 * DINN) + DINN + d];
            float y = (p + xv * Dd) * (res * sigmoidf_(res));
            h_y[row * DINN + d] = __float2half(y);
        }
    }
}

// ---------------- final mean over L ----------------
__global__ void mean_kernel(float* __restrict__ out) {
    int idx = blockIdx.x * blockDim.x + threadIdx.x;
    if (idx >= BATCH * EMBED) return;
    int b = idx / EMBED, e = idx % EMBED;
    float s = 0.0f;
    for (int l = 0; l < LL; l++)
        s += g_xp[((size_t)(b * LL + l)) * EMBED + e];
    out[idx] = s / (float)LL;
}

// ---------------- host helpers ----------------
static inline void launch_gemm(const __half* A, int lda, const __half* B,
                               float* C, __half* Ch,
                               int M, int N, int K,
                               const float* bias, int act, int beta, int splitk = 1)
{
    dim3 grid((N + TMt - 1) / TNt, (M + TMt - 1) / TMt, splitk);
    tc_gemm_nt<<<grid, 256, SMEMSZ>>>(A, lda, B, C, Ch, M, N, K, bias, act, beta);
}
static inline void launch_f2h(const float* src, __half* dst, size_t n) {
    int n4 = (int)(n / 4);
    f2h_kernel<<<(n4 + 255) / 256, 256>>>(src, dst, n4);
}

extern "C" void kernel_launch(void* const* d_in, const int* in_sizes, int n_in,
                              void* d_out, int out_size)
{
    const bool dictOrder = (in_sizes[14] == 2 * DINN * DSTt);

    const float* x          = (const float*)d_in[0];
    const float* abcde_feat = (const float*)d_in[1];
    const float* patch_w    = (const float*)d_in[2];
    const float* patch_b    = (const float*)d_in[3];
    const float* pos_embed  = (const float*)d_in[4];
    const float* abcde_w    = (const float*)d_in[5];
    const float* abcde_b    = (const float*)d_in[6];
    const float* ln_w       = (const float*)d_in[7];
    const float* ln_b       = (const float*)d_in[8];
    const float* in_proj_w  = (const float*)d_in[9];
    const float* conv_w     = (const float*)d_in[10];
    const float* conv_b     = (const float*)d_in[11];
    const float* x_proj_w   = (const float*)d_in[12];
    const float* dt_proj_w  = (const float*)d_in[13];
    const float* dt_proj_b  = dictOrder ? (const float*)d_in[21] : (const float*)d_in[14];
    const float* A_log      = dictOrder ? (const float*)d_in[14] : (const float*)d_in[15];
    const float* D_param    = dictOrder ? (const float*)d_in[15] : (const float*)d_in[16];
    const float* out_proj_w = dictOrder ? (const float*)d_in[16] : (const float*)d_in[17];
    const float* proj_w     = dictOrder ? (const float*)d_in[17] : (const float*)d_in[18];
    const float* proj_b     = dictOrder ? (const float*)d_in[18] : (const float*)d_in[19];
    const float* norm_w     = dictOrder ? (const float*)d_in[19] : (const float*)d_in[20];
    const float* norm_b     = dictOrder ? (const float*)d_in[20] : (const float*)d_in[21];

    float* out = (float*)d_out;

    float *p_xm, *p_xr, *p_xs, *p_dbl, *p_dt, *p_xe, *p_xp, *p_split;
    cudaGetSymbolAddress((void**)&p_xm,  g_xm);
    cudaGetSymbolAddress((void**)&p_xr,  g_xr);
    cudaGetSymbolAddress((void**)&p_xs,  g_xs);
    cudaGetSymbolAddress((void**)&p_dbl, g_dbl);
    cudaGetSymbolAddress((void**)&p_dt,  g_dt);
    cudaGetSymbolAddress((void**)&p_xe,  g_xe);
    cudaGetSymbolAddress((void**)&p_xp,  g_xp);
    cudaGetSymbolAddress((void**)&p_split, g_split);
    __half *ph_col, *ph_xln, *ph_xs, *ph_dbl, *ph_y, *ph_xm;
    __half *ph_patchw, *ph_inw, *ph_xpw, *ph_dtw, *ph_outw, *ph_projw;
    cudaGetSymbolAddress((void**)&ph_col, h_col);
    cudaGetSymbolAddress((void**)&ph_xln, h_xln);
    cudaGetSymbolAddress((void**)&ph_xs,  h_xs);
    cudaGetSymbolAddress((void**)&ph_dbl, h_dbl);
    cudaGetSymbolAddress((void**)&ph_y,   h_y);
    cudaGetSymbolAddress((void**)&ph_xm,  h_xm);
    cudaGetSymbolAddress((void**)&ph_patchw, h_patchw);
    cudaGetSymbolAddress((void**)&ph_inw,  h_inw);
    cudaGetSymbolAddress((void**)&ph_xpw,  h_xpw);
    cudaGetSymbolAddress((void**)&ph_dtw,  h_dtw);
    cudaGetSymbolAddress((void**)&ph_outw, h_outw);
    cudaGetSymbolAddress((void**)&ph_projw, h_projw);

    cudaFuncSetAttribute(tc_gemm_nt, cudaFuncAttributeMaxDynamicSharedMemorySize, SMEMSZ);

    // 0. weight conversions (every call; weights are inputs)
    launch_f2h(patch_w,    ph_patchw, (size_t)EMBED * EMBED);
    launch_f2h(in_proj_w,  ph_inw,   (size_t)2 * 2 * DINN * DIMM);
    launch_f2h(x_proj_w,   ph_xpw,   (size_t)2 * XPROJ_N * DINN);
    launch_f2h(dt_proj_w,  ph_dtw,   (size_t)2 * DINN * DTRr);
    launch_f2h(out_proj_w, ph_outw,  (size_t)2 * DIMM * DINN);
    launch_f2h(proj_w,     ph_projw, (size_t)EMBED * DIMM);

    // 1. index tables
    compute_indices_kernel<<<1, 256>>>();

    // 2. patch embedding
    im2col_kernel<<<(MROWS * EMBED + 255) / 256, 256>>>(x);
    launch_gemm(ph_col, EMBED, ph_patchw, p_xe, nullptr,
                MROWS, EMBED, EMBED, patch_b, 0, 0);
    add_pos_ab_kernel<<<(MROWS * EMBED + 255) / 256, 256>>>(pos_embed, abcde_feat, abcde_w, abcde_b);
    gather_kernel<<<(MROWS * DIMM + 255) / 256, 256>>>();

    // 3. mamba layers
    for (int l = 0; l < 2; l++) {
        const __half* w_in  = ph_inw  + (size_t)l * 2 * DINN * DIMM;
        const float*  w_cv  = conv_w  + (size_t)l * DINN * DCONV;
        const float*  b_cv  = conv_b  + (size_t)l * DINN;
        const __half* w_xp  = ph_xpw  + (size_t)l * XPROJ_N * DINN;
        const __half* w_dt  = ph_dtw  + (size_t)l * DINN * DTRr;
        const float*  b_dt  = dt_proj_b + (size_t)l * DINN;
        const __half* w_out = ph_outw + (size_t)l * DIMM * DINN;
        const float*  Al    = A_log   + (size_t)l * DINN * DSTt;
        const float*  Dl    = D_param + (size_t)l * DINN;

        ln_kernel<<<MROWS, 256>>>(p_xm, nullptr, ph_xln,
                                  ln_w + l * DIMM, ln_b + l * DIMM, DIMM);

        // in_proj: [392,3072] x [12288,3072]^T -> fp32 xr
        launch_gemm(ph_xln, DIMM, w_in, p_xr, nullptr,
                    MROWS, 2 * DINN, DIMM, nullptr, 0, 0);

        conv_silu_kernel<<<(MROWS * DINN + 255) / 256, 256>>>(w_cv, b_cv);

        // x_proj: [392,6144] x [224,6144]^T, split-K 8 -> reduce -> dbl (fp32 + fp16)
        launch_gemm(ph_xs, DINN, w_xp, p_split, nullptr,
                    MROWS, XPROJ_N, DINN, nullptr, 0, 0, 8);
        reduce_split_kernel<<<(MROWS * XPROJ_N + 255) / 256, 256>>>(
            p_split, p_dbl, ph_dbl, nullptr, 8, MROWS * XPROJ_N, XPROJ_N);

        // dt_proj + bias + softplus: [392,192] x [6144,192]^T -> fp32 dt
        launch_gemm(ph_dbl, XPROJ_N, w_dt, p_dt, nullptr,
                    MROWS, DINN, DTRr, b_dt, 1, 0);

        scan_kernel<<<(BATCH * DINN * DSTt) / 256, 256>>>(Al, Dl);

        // out_proj + residual accumulate into xm (+ fp16 mirror for final proj)
        launch_gemm(ph_y, DINN, w_out, p_xm, ph_xm,
                    MROWS, DIMM, DINN, nullptr, 0, 1);
    }

    // 4. final projection (split-K 4) + LN + mean
    launch_gemm(ph_xm, DIMM, ph_projw, p_split, nullptr,
                MROWS, EMBED, DIMM, nullptr, 0, 0, 4);
    reduce_split_kernel<<<(MROWS * EMBED + 255) / 256, 256>>>(
        p_split, p_xp, nullptr, proj_b, 4, MROWS * EMBED, EMBED);
    ln_kernel<<<MROWS, 256>>>(p_xp, p_xp, nullptr, norm_w, norm_b, EMBED);
    mean_kernel<<<(BATCH * EMBED + 255) / 256, 256>>>(out);

    (void)n_in; (void)out_size;
}